// round 10
// baseline (speedup 1.0000x reference)
#include <cuda_runtime.h>
#include <math_constants.h>
#include <cstdint>

#define SEQ    2048
#define BATCH  2
#define NHEADS 8
#define DMODEL 512
#define HDIM   64

// Scratch (allocation-free): 4 x 8MB
__device__ float g_Q[BATCH * SEQ * DMODEL];
__device__ float g_K[BATCH * SEQ * DMODEL];
__device__ float g_V[BATCH * SEQ * DMODEL];
__device__ float g_CTX[BATCH * SEQ * DMODEL];

// ---------------------------------------------------------------------------
// tf32 helpers
// ---------------------------------------------------------------------------
__device__ __forceinline__ float tf32hi(float x) {
    uint32_t u;
    asm("cvt.rna.tf32.f32 %0, %1;" : "=r"(u) : "f"(x));
    return __uint_as_float(u);
}

// D += A * B  (m16n8k8, row.col, tf32 in / f32 accum)
__device__ __forceinline__ void mma8(float* c, const uint32_t* a, const uint32_t* b) {
    asm volatile(
        "mma.sync.aligned.m16n8k8.row.col.f32.tf32.tf32.f32 "
        "{%0,%1,%2,%3}, {%4,%5,%6,%7}, {%8,%9}, {%0,%1,%2,%3};"
        : "+f"(c[0]), "+f"(c[1]), "+f"(c[2]), "+f"(c[3])
        : "r"(a[0]), "r"(a[1]), "r"(a[2]), "r"(a[3]), "r"(b[0]), "r"(b[1]));
}

// ---------------------------------------------------------------------------
// 3xTF32 GEMM (unchanged from R8): Y = (X @ W + bias) * scale
// ---------------------------------------------------------------------------
#define SA 36
#define SB 136

__global__ __launch_bounds__(256) void gemm_tf32_kernel(
    const float* __restrict__ X, const float* __restrict__ W,
    const float* __restrict__ bias, float* __restrict__ Y,
    int M, int N, int K, float scale)
{
    extern __shared__ float sm[];
    float* Ah = sm;
    float* Al = sm + 128 * SA;
    float* Bh = sm + 2 * 128 * SA;
    float* Bl = sm + 2 * 128 * SA + 32 * SB;

    const int bm   = blockIdx.y * 128;
    const int bn   = blockIdx.x * 128;
    const int tid  = threadIdx.x;
    const int warp = tid >> 5;
    const int lane = tid & 31;
    const int g    = lane >> 2;
    const int tig  = lane & 3;
    const int wm   = warp >> 1;
    const int wn   = warp & 1;

    float C[2][8][4];
#pragma unroll
    for (int s = 0; s < 2; s++)
#pragma unroll
        for (int n = 0; n < 8; n++)
#pragma unroll
            for (int j = 0; j < 4; j++) C[s][n][j] = 0.f;

    for (int k0 = 0; k0 < K; k0 += 32) {
#pragma unroll
        for (int it = 0; it < 4; it++) {
            int idx = tid + it * 256;
            int r   = idx >> 3;
            int c4  = (idx & 7) << 2;
            float4 v = *(const float4*)&X[(size_t)(bm + r) * K + k0 + c4];
            float4 h, l;
            h.x = tf32hi(v.x); l.x = v.x - h.x;
            h.y = tf32hi(v.y); l.y = v.y - h.y;
            h.z = tf32hi(v.z); l.z = v.z - h.z;
            h.w = tf32hi(v.w); l.w = v.w - h.w;
            *(float4*)&Ah[r * SA + c4] = h;
            *(float4*)&Al[r * SA + c4] = l;
        }
#pragma unroll
        for (int it = 0; it < 4; it++) {
            int idx = tid + it * 256;
            int r   = idx >> 5;
            int c4  = (idx & 31) << 2;
            float4 v = *(const float4*)&W[(size_t)(k0 + r) * N + bn + c4];
            float4 h, l;
            h.x = tf32hi(v.x); l.x = v.x - h.x;
            h.y = tf32hi(v.y); l.y = v.y - h.y;
            h.z = tf32hi(v.z); l.z = v.z - h.z;
            h.w = tf32hi(v.w); l.w = v.w - h.w;
            *(float4*)&Bh[r * SB + c4] = h;
            *(float4*)&Bl[r * SB + c4] = l;
        }
        __syncthreads();

#pragma unroll
        for (int kc = 0; kc < 4; kc++) {
            uint32_t ah[2][4], al[2][4];
#pragma unroll
            for (int s = 0; s < 2; s++) {
                int row = wm * 32 + s * 16 + g;
                int dc  = kc * 8 + tig;
                ah[s][0] = __float_as_uint(Ah[row * SA + dc]);
                ah[s][1] = __float_as_uint(Ah[(row + 8) * SA + dc]);
                ah[s][2] = __float_as_uint(Ah[row * SA + dc + 4]);
                ah[s][3] = __float_as_uint(Ah[(row + 8) * SA + dc + 4]);
                al[s][0] = __float_as_uint(Al[row * SA + dc]);
                al[s][1] = __float_as_uint(Al[(row + 8) * SA + dc]);
                al[s][2] = __float_as_uint(Al[row * SA + dc + 4]);
                al[s][3] = __float_as_uint(Al[(row + 8) * SA + dc + 4]);
            }
#pragma unroll
            for (int n = 0; n < 8; n++) {
                int col = wn * 64 + n * 8 + g;
                uint32_t bh[2], bl[2];
                bh[0] = __float_as_uint(Bh[(kc * 8 + tig) * SB + col]);
                bh[1] = __float_as_uint(Bh[(kc * 8 + tig + 4) * SB + col]);
                bl[0] = __float_as_uint(Bl[(kc * 8 + tig) * SB + col]);
                bl[1] = __float_as_uint(Bl[(kc * 8 + tig + 4) * SB + col]);
#pragma unroll
                for (int s = 0; s < 2; s++) {
                    mma8(C[s][n], ah[s], bh);
                    mma8(C[s][n], ah[s], bl);
                    mma8(C[s][n], al[s], bh);
                }
            }
        }
        __syncthreads();
    }

#pragma unroll
    for (int s = 0; s < 2; s++) {
#pragma unroll
        for (int n = 0; n < 8; n++) {
            int row = bm + wm * 32 + s * 16 + g;
            int col = bn + wn * 64 + n * 8 + 2 * tig;
            float b0 = bias[col], b1 = bias[col + 1];
            float2 o;
            o.x = (C[s][n][0] + b0) * scale;
            o.y = (C[s][n][1] + b1) * scale;
            *(float2*)&Y[(size_t)row * N + col] = o;
            o.x = (C[s][n][2] + b0) * scale;
            o.y = (C[s][n][3] + b1) * scale;
            *(float2*)&Y[(size_t)(row + 8) * N + col] = o;
        }
    }
}

// ---------------------------------------------------------------------------
// Flash attention, tensor-core, fragment-packed smem.
// CTA = 128 q-rows, one (b,h). 8 warps x 16 rows. 2 CTAs/SM.
// QK: Q hi/lo (packed frags, staged once) x K rounded tf32  -> 2 mmas, err ~u^2
// PV: P hi/lo x V rounded tf32                              -> 2 mmas
// Smem layouts (floats):
//   QFh[(w*8+c)*32+lane] float4 : Q hi a-frags    (8192 fl)
//   QFl  same, lo                                  (8192 fl)
//   KF [(c*8+n)*32 + (lane^(c<<2))] float2 = (K[n8+g][c8+tig], [..][+4]) (4096)
//   VF [(c*8+n)*32 + (lane^(n<<2))] float2 = (V[c8+tig][n8+g], [+4][..]) (4096)
// ---------------------------------------------------------------------------
__global__ __launch_bounds__(256, 2) void flash_tf32_kernel(
    const int* __restrict__ mask,
    const float* __restrict__ bias)
{
    extern __shared__ float sm[];
    float* QFh = sm;                 // 8192 floats
    float* QFl = sm + 8192;          // 8192
    float* KF  = sm + 16384;         // 4096
    float* VF  = sm + 20480;         // 4096

    const int b    = blockIdx.x;
    const int q0   = blockIdx.y * 128;
    const int h    = blockIdx.z;
    const int tid  = threadIdx.x;
    const int warp = tid >> 5;
    const int lane = tid & 31;
    const int g    = lane >> 2;
    const int tig  = lane & 3;

    const float* Qg = g_Q + (size_t)b * SEQ * DMODEL + (size_t)h * HDIM;
    const float* Kg = g_K + (size_t)b * SEQ * DMODEL + (size_t)h * HDIM;
    const float* Vg = g_V + (size_t)b * SEQ * DMODEL + (size_t)h * HDIM;
    const float* biasH = bias + (size_t)h * SEQ * SEQ;

    // ---- Stage Q once: split hi/lo, write directly in a-frag layout ----
#pragma unroll
    for (int it = 0; it < 8; it++) {
        int idx = tid + it * 256;          // 0..2047 float4s (128 rows x 16)
        int r   = idx >> 4;                // q-row 0..127
        int c4  = (idx & 15) << 2;         // d 0,4,..,60
        float4 v = *(const float4*)&Qg[(size_t)(q0 + r) * DMODEL + c4];
        int w   = r >> 4;
        int rg  = (r >> 3) & 1;            // 0: rows g, 1: rows g+8
        int gg  = r & 7;
        int c   = c4 >> 3;
        int hi4 = (c4 >> 2) & 1;           // 0: d, 1: d+4 slot
        int comp = rg + 2 * hi4;
        int base = (((w * 8 + c) * 32) + gg * 4) * 4;  // float idx of float4 slot, tig=0
        float vv[4] = {v.x, v.y, v.z, v.w};
#pragma unroll
        for (int j = 0; j < 4; j++) {      // j = tig
            float hi = tf32hi(vv[j]);
            float lo = tf32hi(vv[j] - hi);
            QFh[base + j * 4 + comp] = hi;
            QFl[base + j * 4 + comp] = lo;
        }
    }

    float O[8][4];
#pragma unroll
    for (int n = 0; n < 8; n++)
#pragma unroll
        for (int j = 0; j < 4; j++) O[n][j] = 0.f;
    float m0 = -CUDART_INF_F, m1 = -CUDART_INF_F, l0 = 0.f, l1 = 0.f;

    const int row0 = q0 + warp * 16 + g;   // global q-rows (bias/mask)
    const int row1 = row0 + 8;

    for (int k0 = 0; k0 < SEQ; k0 += 64) {
        // ---- Stage K (rounded) and V (rounded) into packed frag layouts ----
#pragma unroll
        for (int it = 0; it < 4; it++) {
            int idx = tid + it * 256;       // 0..1023 float4s (64 rows x 16)
            int r   = idx >> 4;             // key 0..63
            int c4  = (idx & 15) << 2;      // d
            float4 kv = *(const float4*)&Kg[(size_t)(k0 + r) * DMODEL + c4];
            float4 vv = *(const float4*)&Vg[(size_t)(k0 + r) * DMODEL + c4];
            // K: element (key r, d) -> c=d>>3, tig=d&3(=j), half=(d>>2)&1
            {
                int nk = r >> 3, gk = r & 7;
                int c  = c4 >> 3;
                int half = (c4 >> 2) & 1;
                int blk  = (c * 8 + nk) * 32;
                float kk[4] = {kv.x, kv.y, kv.z, kv.w};
#pragma unroll
                for (int j = 0; j < 4; j++) {
                    int slot = (gk * 4 + j) ^ (c << 2);
                    KF[(blk + slot) * 2 + half] = tf32hi(kk[j]);
                }
            }
            // V: element (key r, d) -> c=r>>3, tigv=r&3, comp=(r>>2)&1; n=d>>3, g=d&7
            {
                int cv = r >> 3, tv = r & 3, comp = (r >> 2) & 1;
                int nv = c4 >> 3;
                int gb = c4 & 7;            // 0 or 4
                float vvv[4] = {vv.x, vv.y, vv.z, vv.w};
#pragma unroll
                for (int j = 0; j < 4; j++) {
                    int slot = ((gb + j) * 4 + tv) ^ (nv << 2);
                    VF[((cv * 8 + nv) * 32 + slot) * 2 + comp] = tf32hi(vvv[j]);
                }
            }
        }
        __syncthreads();

        // ---- S = Q @ K^T  (Qh+Ql) x Kr ----
        float S[8][4];
#pragma unroll
        for (int n = 0; n < 8; n++)
            S[n][0] = S[n][1] = S[n][2] = S[n][3] = 0.f;

#pragma unroll
        for (int c = 0; c < 8; c++) {
            float4 qh = *(float4*)&QFh[((warp * 8 + c) * 32 + lane) * 4];
            float4 ql = *(float4*)&QFl[((warp * 8 + c) * 32 + lane) * 4];
            const int lx = (lane ^ (c << 2));
#pragma unroll
            for (int n = 0; n < 8; n++) {
                float2 kk = *(float2*)&KF[((c * 8 + n) * 32 + lx) * 2];
                mma8(S[n], (const uint32_t*)&qh, (const uint32_t*)&kk);
                mma8(S[n], (const uint32_t*)&ql, (const uint32_t*)&kk);
            }
        }

        // ---- bias + mask ----
#pragma unroll
        for (int n = 0; n < 8; n++) {
            int col = k0 + n * 8 + 2 * tig;
            float2 bv0 = *(const float2*)&biasH[(size_t)row0 * SEQ + col];
            int2   mv0 = *(const int2*)  &mask [(size_t)row0 * SEQ + col];
            float2 bv1 = *(const float2*)&biasH[(size_t)row1 * SEQ + col];
            int2   mv1 = *(const int2*)  &mask [(size_t)row1 * SEQ + col];
            S[n][0] = mv0.x ? S[n][0] + bv0.x : -CUDART_INF_F;
            S[n][1] = mv0.y ? S[n][1] + bv0.y : -CUDART_INF_F;
            S[n][2] = mv1.x ? S[n][2] + bv1.x : -CUDART_INF_F;
            S[n][3] = mv1.y ? S[n][3] + bv1.y : -CUDART_INF_F;
        }

        // ---- online softmax (rows g / g+8, quad-wide reductions) ----
        float mx0 = -CUDART_INF_F, mx1 = -CUDART_INF_F;
#pragma unroll
        for (int n = 0; n < 8; n++) {
            mx0 = fmaxf(mx0, fmaxf(S[n][0], S[n][1]));
            mx1 = fmaxf(mx1, fmaxf(S[n][2], S[n][3]));
        }
        mx0 = fmaxf(mx0, __shfl_xor_sync(0xffffffffu, mx0, 1));
        mx0 = fmaxf(mx0, __shfl_xor_sync(0xffffffffu, mx0, 2));
        mx1 = fmaxf(mx1, __shfl_xor_sync(0xffffffffu, mx1, 1));
        mx1 = fmaxf(mx1, __shfl_xor_sync(0xffffffffu, mx1, 2));

        float mn0 = fmaxf(m0, mx0), mn1 = fmaxf(m1, mx1);
        float ref0 = (mn0 == -CUDART_INF_F) ? 0.f : mn0;
        float ref1 = (mn1 == -CUDART_INF_F) ? 0.f : mn1;
        float alpha0 = __expf(m0 - ref0);
        float alpha1 = __expf(m1 - ref1);
        m0 = mn0; m1 = mn1;

        float rs0 = 0.f, rs1 = 0.f;
#pragma unroll
        for (int n = 0; n < 8; n++) {
            S[n][0] = __expf(S[n][0] - ref0);
            S[n][1] = __expf(S[n][1] - ref0);
            S[n][2] = __expf(S[n][2] - ref1);
            S[n][3] = __expf(S[n][3] - ref1);
            rs0 += S[n][0] + S[n][1];
            rs1 += S[n][2] + S[n][3];
        }
        rs0 += __shfl_xor_sync(0xffffffffu, rs0, 1);
        rs0 += __shfl_xor_sync(0xffffffffu, rs0, 2);
        rs1 += __shfl_xor_sync(0xffffffffu, rs1, 1);
        rs1 += __shfl_xor_sync(0xffffffffu, rs1, 2);
        l0 = l0 * alpha0 + rs0;
        l1 = l1 * alpha1 + rs1;

#pragma unroll
        for (int n = 0; n < 8; n++) {
            O[n][0] *= alpha0; O[n][1] *= alpha0;
            O[n][2] *= alpha1; O[n][3] *= alpha1;
        }

        // ---- O += P @ V (P hi/lo x V rounded). A-frags via quad shuffles ----
        const int srcA = (g << 2) | (tig >> 1);
        const int srcB = srcA + 2;
        const bool sel = tig & 1;
#pragma unroll
        for (int c = 0; c < 8; c++) {
            float vA0 = __shfl_sync(0xffffffffu, S[c][0], srcA);
            float vA1 = __shfl_sync(0xffffffffu, S[c][1], srcA);
            float vA2 = __shfl_sync(0xffffffffu, S[c][2], srcA);
            float vA3 = __shfl_sync(0xffffffffu, S[c][3], srcA);
            float vB0 = __shfl_sync(0xffffffffu, S[c][0], srcB);
            float vB1 = __shfl_sync(0xffffffffu, S[c][1], srcB);
            float vB2 = __shfl_sync(0xffffffffu, S[c][2], srcB);
            float vB3 = __shfl_sync(0xffffffffu, S[c][3], srcB);
            float pa0 = sel ? vA1 : vA0;   // (row g,   key c*8+tig)
            float pa1 = sel ? vA3 : vA2;   // (row g+8, key c*8+tig)
            float pa2 = sel ? vB1 : vB0;   // (row g,   key c*8+tig+4)
            float pa3 = sel ? vB3 : vB2;   // (row g+8, key c*8+tig+4)
            uint32_t pah[4], pal[4];
            float h0 = tf32hi(pa0), h1 = tf32hi(pa1), h2 = tf32hi(pa2), h3 = tf32hi(pa3);
            pah[0] = __float_as_uint(h0); pal[0] = __float_as_uint(pa0 - h0);
            pah[1] = __float_as_uint(h1); pal[1] = __float_as_uint(pa1 - h1);
            pah[2] = __float_as_uint(h2); pal[2] = __float_as_uint(pa2 - h2);
            pah[3] = __float_as_uint(h3); pal[3] = __float_as_uint(pa3 - h3);

#pragma unroll
            for (int n = 0; n < 8; n++) {
                float2 vv = *(float2*)&VF[((c * 8 + n) * 32 + (lane ^ (n << 2))) * 2];
                mma8(O[n], pah, (const uint32_t*)&vv);
                mma8(O[n], pal, (const uint32_t*)&vv);
            }
        }
        __syncthreads();   // before next tile's staging overwrites KF/VF
    }

    // ---- epilogue: normalize, write ctx [b, s, h*64+d] ----
    float inv0 = (l0 > 0.f) ? (1.f / l0) : 0.f;
    float inv1 = (l1 > 0.f) ? (1.f / l1) : 0.f;
#pragma unroll
    for (int n = 0; n < 8; n++) {
        int col = h * HDIM + n * 8 + 2 * tig;
        float2 o;
        o.x = O[n][0] * inv0; o.y = O[n][1] * inv0;
        *(float2*)&g_CTX[(size_t)(b * SEQ + row0) * DMODEL + col] = o;
        o.x = O[n][2] * inv1; o.y = O[n][3] * inv1;
        *(float2*)&g_CTX[(size_t)(b * SEQ + row1) * DMODEL + col] = o;
    }
}

// ---------------------------------------------------------------------------
// Launch
// ---------------------------------------------------------------------------
extern "C" void kernel_launch(void* const* d_in, const int* in_sizes, int n_in,
                              void* d_out, int out_size)
{
    const float* k    = (const float*)d_in[0];
    const float* v    = (const float*)d_in[1];
    const float* q    = (const float*)d_in[2];
    const int*   mask = (const int*)d_in[3];
    const float* bias = (const float*)d_in[4];
    const float* Wq   = (const float*)d_in[5];
    const float* bq   = (const float*)d_in[6];
    const float* Wk   = (const float*)d_in[7];
    const float* bk   = (const float*)d_in[8];
    const float* Wv   = (const float*)d_in[9];
    const float* bv   = (const float*)d_in[10];
    const float* Wo   = (const float*)d_in[11];
    const float* bo   = (const float*)d_in[12];
    float* out = (float*)d_out;

    float *pQ, *pK, *pV, *pC;
    cudaGetSymbolAddress((void**)&pQ, g_Q);
    cudaGetSymbolAddress((void**)&pK, g_K);
    cudaGetSymbolAddress((void**)&pV, g_V);
    cudaGetSymbolAddress((void**)&pC, g_CTX);

    const int gemm_smem = (2 * 128 * SA + 2 * 32 * SB) * 4;   // 71680 B
    const int attn_smem = 24576 * 4;                           // 98304 B
    cudaFuncSetAttribute(gemm_tf32_kernel,
                         cudaFuncAttributeMaxDynamicSharedMemorySize, gemm_smem);
    cudaFuncSetAttribute(flash_tf32_kernel,
                         cudaFuncAttributeMaxDynamicSharedMemorySize, attn_smem);

    const int M = BATCH * SEQ;                 // 4096
    dim3 gemm_grid(DMODEL / 128, M / 128);     // (4, 32)
    const float qscale = 0.125f;               // 1/sqrt(64)

    gemm_tf32_kernel<<<gemm_grid, 256, gemm_smem>>>(q, Wq, bq, pQ, M, DMODEL, DMODEL, qscale);
    gemm_tf32_kernel<<<gemm_grid, 256, gemm_smem>>>(k, Wk, bk, pK, M, DMODEL, DMODEL, 1.0f);
    gemm_tf32_kernel<<<gemm_grid, 256, gemm_smem>>>(v, Wv, bv, pV, M, DMODEL, DMODEL, 1.0f);

    dim3 attn_grid(BATCH, SEQ / 128, NHEADS);  // batch fastest -> bias L2 reuse
    flash_tf32_kernel<<<attn_grid, 256, attn_smem>>>(mask, bias);

    gemm_tf32_kernel<<<gemm_grid, 256, gemm_smem>>>(pC, Wo, bo, out, M, DMODEL, DMODEL, 1.0f);
}

// round 12
// speedup vs baseline: 1.0309x; 1.0309x over previous
#include <cuda_runtime.h>
#include <math_constants.h>
#include <cstdint>

#define SEQ    2048
#define BATCH  2
#define NHEADS 8
#define DMODEL 512
#define HDIM   64

// Scratch (allocation-free): 4 x 8MB
__device__ float g_Q[BATCH * SEQ * DMODEL];
__device__ float g_K[BATCH * SEQ * DMODEL];
__device__ float g_V[BATCH * SEQ * DMODEL];
__device__ float g_CTX[BATCH * SEQ * DMODEL];

// ---------------------------------------------------------------------------
// tf32 helpers
// ---------------------------------------------------------------------------
__device__ __forceinline__ float tf32hi(float x) {
    uint32_t u;
    asm("cvt.rna.tf32.f32 %0, %1;" : "=r"(u) : "f"(x));
    return __uint_as_float(u);
}
__device__ __forceinline__ uint32_t tf32u(float x) {
    uint32_t u;
    asm("cvt.rna.tf32.f32 %0, %1;" : "=r"(u) : "f"(x));
    return u;
}

// D += A * B  (m16n8k8, row.col, tf32 in / f32 accum)
__device__ __forceinline__ void mma8(float* c, const uint32_t* a, const uint32_t* b) {
    asm volatile(
        "mma.sync.aligned.m16n8k8.row.col.f32.tf32.tf32.f32 "
        "{%0,%1,%2,%3}, {%4,%5,%6,%7}, {%8,%9}, {%0,%1,%2,%3};"
        : "+f"(c[0]), "+f"(c[1]), "+f"(c[2]), "+f"(c[3])
        : "r"(a[0]), "r"(a[1]), "r"(a[2]), "r"(a[3]), "r"(b[0]), "r"(b[1]));
}

// ---------------------------------------------------------------------------
// 3xTF32 GEMM body: Y = (X @ W + bias) * scale.  M=4096, N=K=512 fixed use.
// 128x128 tile, BK=32, 256 threads = 8 warps (4m x 2n), warp tile 32x64.
// ---------------------------------------------------------------------------
#define SA 36
#define SB 136

__device__ __forceinline__ void gemm_body(
    const float* __restrict__ X, const float* __restrict__ W,
    const float* __restrict__ bias, float* __restrict__ Y,
    int M, int N, int K, float scale, float* sm, int bm, int bn)
{
    float* Ah = sm;
    float* Al = sm + 128 * SA;
    float* Bh = sm + 2 * 128 * SA;
    float* Bl = sm + 2 * 128 * SA + 32 * SB;

    const int tid  = threadIdx.x;
    const int warp = tid >> 5;
    const int lane = tid & 31;
    const int g    = lane >> 2;
    const int tig  = lane & 3;
    const int wm   = warp >> 1;
    const int wn   = warp & 1;

    float C[2][8][4];
#pragma unroll
    for (int s = 0; s < 2; s++)
#pragma unroll
        for (int n = 0; n < 8; n++)
#pragma unroll
            for (int j = 0; j < 4; j++) C[s][n][j] = 0.f;

    for (int k0 = 0; k0 < K; k0 += 32) {
#pragma unroll
        for (int it = 0; it < 4; it++) {
            int idx = tid + it * 256;
            int r   = idx >> 3;
            int c4  = (idx & 7) << 2;
            float4 v = *(const float4*)&X[(size_t)(bm + r) * K + k0 + c4];
            float4 h, l;
            h.x = tf32hi(v.x); l.x = v.x - h.x;
            h.y = tf32hi(v.y); l.y = v.y - h.y;
            h.z = tf32hi(v.z); l.z = v.z - h.z;
            h.w = tf32hi(v.w); l.w = v.w - h.w;
            *(float4*)&Ah[r * SA + c4] = h;
            *(float4*)&Al[r * SA + c4] = l;
        }
#pragma unroll
        for (int it = 0; it < 4; it++) {
            int idx = tid + it * 256;
            int r   = idx >> 5;
            int c4  = (idx & 31) << 2;
            float4 v = *(const float4*)&W[(size_t)(k0 + r) * N + bn + c4];
            float4 h, l;
            h.x = tf32hi(v.x); l.x = v.x - h.x;
            h.y = tf32hi(v.y); l.y = v.y - h.y;
            h.z = tf32hi(v.z); l.z = v.z - h.z;
            h.w = tf32hi(v.w); l.w = v.w - h.w;
            *(float4*)&Bh[r * SB + c4] = h;
            *(float4*)&Bl[r * SB + c4] = l;
        }
        __syncthreads();

#pragma unroll
        for (int kc = 0; kc < 4; kc++) {
            uint32_t ah[2][4], al[2][4];
#pragma unroll
            for (int s = 0; s < 2; s++) {
                int row = wm * 32 + s * 16 + g;
                int dc  = kc * 8 + tig;
                ah[s][0] = __float_as_uint(Ah[row * SA + dc]);
                ah[s][1] = __float_as_uint(Ah[(row + 8) * SA + dc]);
                ah[s][2] = __float_as_uint(Ah[row * SA + dc + 4]);
                ah[s][3] = __float_as_uint(Ah[(row + 8) * SA + dc + 4]);
                al[s][0] = __float_as_uint(Al[row * SA + dc]);
                al[s][1] = __float_as_uint(Al[(row + 8) * SA + dc]);
                al[s][2] = __float_as_uint(Al[row * SA + dc + 4]);
                al[s][3] = __float_as_uint(Al[(row + 8) * SA + dc + 4]);
            }
#pragma unroll
            for (int n = 0; n < 8; n++) {
                int col = wn * 64 + n * 8 + g;
                uint32_t bh[2], bl[2];
                bh[0] = __float_as_uint(Bh[(kc * 8 + tig) * SB + col]);
                bh[1] = __float_as_uint(Bh[(kc * 8 + tig + 4) * SB + col]);
                bl[0] = __float_as_uint(Bl[(kc * 8 + tig) * SB + col]);
                bl[1] = __float_as_uint(Bl[(kc * 8 + tig + 4) * SB + col]);
#pragma unroll
                for (int s = 0; s < 2; s++) {
                    mma8(C[s][n], ah[s], bh);
                    mma8(C[s][n], ah[s], bl);
                    mma8(C[s][n], al[s], bh);
                }
            }
        }
        __syncthreads();
    }

#pragma unroll
    for (int s = 0; s < 2; s++) {
#pragma unroll
        for (int n = 0; n < 8; n++) {
            int row = bm + wm * 32 + s * 16 + g;
            int col = bn + wn * 64 + n * 8 + 2 * tig;
            float b0 = bias[col], b1 = bias[col + 1];
            float2 o;
            o.x = (C[s][n][0] + b0) * scale;
            o.y = (C[s][n][1] + b1) * scale;
            *(float2*)&Y[(size_t)row * N + col] = o;
            o.x = (C[s][n][2] + b0) * scale;
            o.y = (C[s][n][3] + b1) * scale;
            *(float2*)&Y[(size_t)(row + 8) * N + col] = o;
        }
    }
}

// Fused Q/K/V projections: blockIdx.z selects which projection.
__global__ __launch_bounds__(256) void gemm_qkv_kernel(
    const float* __restrict__ q, const float* __restrict__ k, const float* __restrict__ v,
    const float* __restrict__ Wq, const float* __restrict__ Wk, const float* __restrict__ Wv,
    const float* __restrict__ bq, const float* __restrict__ bk, const float* __restrict__ bv,
    float* __restrict__ pQ, float* __restrict__ pK, float* __restrict__ pV)
{
    extern __shared__ float sm[];
    const float *X, *W, *B;
    float* Y;
    float scale;
    if (blockIdx.z == 0)      { X = q; W = Wq; B = bq; Y = pQ; scale = 0.125f; }
    else if (blockIdx.z == 1) { X = k; W = Wk; B = bk; Y = pK; scale = 1.0f; }
    else                      { X = v; W = Wv; B = bv; Y = pV; scale = 1.0f; }
    gemm_body(X, W, B, Y, BATCH * SEQ, DMODEL, DMODEL, scale, sm,
              blockIdx.y * 128, blockIdx.x * 128);
}

// Single GEMM (output projection).
__global__ __launch_bounds__(256) void gemm_tf32_kernel(
    const float* __restrict__ X, const float* __restrict__ W,
    const float* __restrict__ bias, float* __restrict__ Y,
    int M, int N, int K, float scale)
{
    extern __shared__ float sm[];
    gemm_body(X, W, bias, Y, M, N, K, scale, sm, blockIdx.y * 128, blockIdx.x * 128);
}

// ---------------------------------------------------------------------------
// Flash attention (R9 structure + latency hiding).
// CTA = 128 q-rows, one (b,h). 8 warps x 16 rows. 2 CTAs/SM.
// QK: Q rounded tf32 x K hi/lo (2 mmas);  PV: P hi/lo x V rounded (2 mmas).
// Bias prefetched to regs at tile-loop top (covered by staging + QK MMAs);
// mask packed to a 1KB smem bitfield during staging (no gmem on consume path).
// ---------------------------------------------------------------------------
#define SKV 68   // smem row stride (floats)

__global__ __launch_bounds__(256, 2) void flash_tf32_kernel(
    const int* __restrict__ mask,
    const float* __restrict__ bias)
{
    extern __shared__ float sm[];
    float* Qraw = sm;                       // [128][SKV] raw fp32
    float* Khi  = sm + 128 * SKV;           // [64][SKV]
    float* Klo  = Khi + 64 * SKV;
    float* Vhi  = Klo + 64 * SKV;           // rounded V
    uint32_t* Mbits = (uint32_t*)(Vhi + 64 * SKV);  // [128][2] key-bitmask

    const int b    = blockIdx.x;
    const int q0   = blockIdx.y * 128;
    const int h    = blockIdx.z;
    const int tid  = threadIdx.x;
    const int warp = tid >> 5;
    const int lane = tid & 31;
    const int g    = lane >> 2;
    const int tig  = lane & 3;

    const float* Qg = g_Q + (size_t)b * SEQ * DMODEL + (size_t)h * HDIM;
    const float* Kg = g_K + (size_t)b * SEQ * DMODEL + (size_t)h * HDIM;
    const float* Vg = g_V + (size_t)b * SEQ * DMODEL + (size_t)h * HDIM;
    const float* biasH = bias + (size_t)h * SEQ * SEQ;

    // ---- Stage Q tile once (raw fp32) ----
#pragma unroll
    for (int it = 0; it < 8; it++) {
        int idx = tid + it * 256;          // 0..2047
        int r   = idx >> 4;
        int c4  = (idx & 15) << 2;
        *(float4*)&Qraw[r * SKV + c4] =
            *(const float4*)&Qg[(size_t)(q0 + r) * DMODEL + c4];
    }

    float O[8][4];
#pragma unroll
    for (int n = 0; n < 8; n++)
#pragma unroll
        for (int j = 0; j < 4; j++) O[n][j] = 0.f;
    float m0 = -CUDART_INF_F, m1 = -CUDART_INF_F, l0 = 0.f, l1 = 0.f;

    const int r1   = warp * 16 + g;        // CTA-local q-rows
    const int r2   = r1 + 8;
    const int row0 = q0 + r1;              // global q-rows
    const int row1 = row0 + 8;

    // mask-staging mapping: thread -> (row, 32-key word)
    const int mr = tid >> 1;               // 0..127
    const int mw = tid & 1;                // 0..1

    for (int k0 = 0; k0 < SEQ; k0 += 64) {
        // ---- Prefetch bias for this tile (latency covered by staging + QK) ----
        float2 bv0[8], bv1[8];
#pragma unroll
        for (int n = 0; n < 8; n++) {
            int col = k0 + n * 8 + 2 * tig;
            bv0[n] = *(const float2*)&biasH[(size_t)row0 * SEQ + col];
            bv1[n] = *(const float2*)&biasH[(size_t)row1 * SEQ + col];
        }

        // ---- Stage mask bits: 32 ints -> 1 word per thread ----
        {
            const int4* mrow = (const int4*)&mask[(size_t)(q0 + mr) * SEQ + k0 + mw * 32];
            uint32_t bits = 0;
#pragma unroll
            for (int i = 0; i < 8; i++) {
                int4 mvv = mrow[i];
                bits |= (uint32_t)(mvv.x != 0) << (4 * i);
                bits |= (uint32_t)(mvv.y != 0) << (4 * i + 1);
                bits |= (uint32_t)(mvv.z != 0) << (4 * i + 2);
                bits |= (uint32_t)(mvv.w != 0) << (4 * i + 3);
            }
            Mbits[tid] = bits;   // Mbits[row*2 + word]
        }

        // ---- Stage K (split hi/lo) and V (rounded) ----
#pragma unroll
        for (int it = 0; it < 4; it++) {
            int idx = tid + it * 256;       // 0..1023
            int r   = idx >> 4;             // key 0..63
            int c4  = (idx & 15) << 2;      // d
            float4 kv = *(const float4*)&Kg[(size_t)(k0 + r) * DMODEL + c4];
            float4 vv = *(const float4*)&Vg[(size_t)(k0 + r) * DMODEL + c4];
            float4 hh, ll;
            hh.x = tf32hi(kv.x); ll.x = kv.x - hh.x;
            hh.y = tf32hi(kv.y); ll.y = kv.y - hh.y;
            hh.z = tf32hi(kv.z); ll.z = kv.z - hh.z;
            hh.w = tf32hi(kv.w); ll.w = kv.w - hh.w;
            *(float4*)&Khi[r * SKV + c4] = hh;
            *(float4*)&Klo[r * SKV + c4] = ll;
            hh.x = tf32hi(vv.x); hh.y = tf32hi(vv.y);
            hh.z = tf32hi(vv.z); hh.w = tf32hi(vv.w);
            *(float4*)&Vhi[r * SKV + c4] = hh;
        }
        __syncthreads();

        // ---- read this thread's mask words (smem, cheap) ----
        uint32_t mA0 = Mbits[r1 * 2],     mA1 = Mbits[r1 * 2 + 1];
        uint32_t mB0 = Mbits[r2 * 2],     mB1 = Mbits[r2 * 2 + 1];

        // ---- S = Q @ K^T (Q rounded x K hi/lo) ----
        float S[8][4];
#pragma unroll
        for (int n = 0; n < 8; n++)
            S[n][0] = S[n][1] = S[n][2] = S[n][3] = 0.f;

#pragma unroll
        for (int c = 0; c < 8; c++) {
            int dc = c * 8 + tig;
            uint32_t a[4];
            a[0] = tf32u(Qraw[r1 * SKV + dc]);
            a[1] = tf32u(Qraw[r2 * SKV + dc]);
            a[2] = tf32u(Qraw[r1 * SKV + dc + 4]);
            a[3] = tf32u(Qraw[r2 * SKV + dc + 4]);
#pragma unroll
            for (int n = 0; n < 8; n++) {
                int krow = n * 8 + g;
                uint32_t bh[2], bl[2];
                bh[0] = __float_as_uint(Khi[krow * SKV + dc]);
                bh[1] = __float_as_uint(Khi[krow * SKV + dc + 4]);
                bl[0] = __float_as_uint(Klo[krow * SKV + dc]);
                bl[1] = __float_as_uint(Klo[krow * SKV + dc + 4]);
                mma8(S[n], a, bh);
                mma8(S[n], a, bl);
            }
        }

        // ---- bias (prefetched regs) + mask (smem bits) ----
#pragma unroll
        for (int n = 0; n < 8; n++) {
            uint32_t wA = (n >> 2) ? mA1 : mA0;
            uint32_t wB = (n >> 2) ? mB1 : mB0;
            int bit = (n & 3) * 8 + 2 * tig;
            S[n][0] = ((wA >> bit) & 1u)       ? S[n][0] + bv0[n].x : -CUDART_INF_F;
            S[n][1] = ((wA >> (bit + 1)) & 1u) ? S[n][1] + bv0[n].y : -CUDART_INF_F;
            S[n][2] = ((wB >> bit) & 1u)       ? S[n][2] + bv1[n].x : -CUDART_INF_F;
            S[n][3] = ((wB >> (bit + 1)) & 1u) ? S[n][3] + bv1[n].y : -CUDART_INF_F;
        }

        // ---- online softmax (rows g / g+8, quad-wide reductions) ----
        float mx0 = -CUDART_INF_F, mx1 = -CUDART_INF_F;
#pragma unroll
        for (int n = 0; n < 8; n++) {
            mx0 = fmaxf(mx0, fmaxf(S[n][0], S[n][1]));
            mx1 = fmaxf(mx1, fmaxf(S[n][2], S[n][3]));
        }
        mx0 = fmaxf(mx0, __shfl_xor_sync(0xffffffffu, mx0, 1));
        mx0 = fmaxf(mx0, __shfl_xor_sync(0xffffffffu, mx0, 2));
        mx1 = fmaxf(mx1, __shfl_xor_sync(0xffffffffu, mx1, 1));
        mx1 = fmaxf(mx1, __shfl_xor_sync(0xffffffffu, mx1, 2));

        float mn0 = fmaxf(m0, mx0), mn1 = fmaxf(m1, mx1);
        float ref0 = (mn0 == -CUDART_INF_F) ? 0.f : mn0;
        float ref1 = (mn1 == -CUDART_INF_F) ? 0.f : mn1;
        float alpha0 = __expf(m0 - ref0);
        float alpha1 = __expf(m1 - ref1);
        m0 = mn0; m1 = mn1;

        float rs0 = 0.f, rs1 = 0.f;
#pragma unroll
        for (int n = 0; n < 8; n++) {
            S[n][0] = __expf(S[n][0] - ref0);
            S[n][1] = __expf(S[n][1] - ref0);
            S[n][2] = __expf(S[n][2] - ref1);
            S[n][3] = __expf(S[n][3] - ref1);
            rs0 += S[n][0] + S[n][1];
            rs1 += S[n][2] + S[n][3];
        }
        rs0 += __shfl_xor_sync(0xffffffffu, rs0, 1);
        rs0 += __shfl_xor_sync(0xffffffffu, rs0, 2);
        rs1 += __shfl_xor_sync(0xffffffffu, rs1, 1);
        rs1 += __shfl_xor_sync(0xffffffffu, rs1, 2);
        l0 = l0 * alpha0 + rs0;
        l1 = l1 * alpha1 + rs1;

#pragma unroll
        for (int n = 0; n < 8; n++) {
            O[n][0] *= alpha0; O[n][1] *= alpha0;
            O[n][2] *= alpha1; O[n][3] *= alpha1;
        }

        // ---- O += P @ V (P hi/lo x V rounded). A-frags via quad shuffles ----
        const int srcA = (g << 2) | (tig >> 1);
        const int srcB = srcA + 2;
        const bool sel = tig & 1;
#pragma unroll
        for (int c = 0; c < 8; c++) {
            float vA0 = __shfl_sync(0xffffffffu, S[c][0], srcA);
            float vA1 = __shfl_sync(0xffffffffu, S[c][1], srcA);
            float vA2 = __shfl_sync(0xffffffffu, S[c][2], srcA);
            float vA3 = __shfl_sync(0xffffffffu, S[c][3], srcA);
            float vB0 = __shfl_sync(0xffffffffu, S[c][0], srcB);
            float vB1 = __shfl_sync(0xffffffffu, S[c][1], srcB);
            float vB2 = __shfl_sync(0xffffffffu, S[c][2], srcB);
            float vB3 = __shfl_sync(0xffffffffu, S[c][3], srcB);
            float pa0 = sel ? vA1 : vA0;   // (row g,   key c*8+tig)
            float pa1 = sel ? vA3 : vA2;   // (row g+8, key c*8+tig)
            float pa2 = sel ? vB1 : vB0;   // (row g,   key c*8+tig+4)
            float pa3 = sel ? vB3 : vB2;   // (row g+8, key c*8+tig+4)
            uint32_t pah[4], pal[4];
            float h0 = tf32hi(pa0), h1 = tf32hi(pa1), h2 = tf32hi(pa2), h3 = tf32hi(pa3);
            pah[0] = __float_as_uint(h0); pal[0] = __float_as_uint(pa0 - h0);
            pah[1] = __float_as_uint(h1); pal[1] = __float_as_uint(pa1 - h1);
            pah[2] = __float_as_uint(h2); pal[2] = __float_as_uint(pa2 - h2);
            pah[3] = __float_as_uint(h3); pal[3] = __float_as_uint(pa3 - h3);

            int vrow = c * 8 + tig;   // key
#pragma unroll
            for (int n = 0; n < 8; n++) {
                int vcol = n * 8 + g; // d
                uint32_t bh[2];
                bh[0] = __float_as_uint(Vhi[vrow * SKV + vcol]);
                bh[1] = __float_as_uint(Vhi[(vrow + 4) * SKV + vcol]);
                mma8(O[n], pah, bh);
                mma8(O[n], pal, bh);
            }
        }
        __syncthreads();   // before next tile's staging
    }

    // ---- epilogue: normalize, write ctx [b, s, h*64+d] ----
    float inv0 = (l0 > 0.f) ? (1.f / l0) : 0.f;
    float inv1 = (l1 > 0.f) ? (1.f / l1) : 0.f;
#pragma unroll
    for (int n = 0; n < 8; n++) {
        int col = h * HDIM + n * 8 + 2 * tig;
        float2 o;
        o.x = O[n][0] * inv0; o.y = O[n][1] * inv0;
        *(float2*)&g_CTX[(size_t)(b * SEQ + row0) * DMODEL + col] = o;
        o.x = O[n][2] * inv1; o.y = O[n][3] * inv1;
        *(float2*)&g_CTX[(size_t)(b * SEQ + row1) * DMODEL + col] = o;
    }
}

// ---------------------------------------------------------------------------
// Launch
// ---------------------------------------------------------------------------
extern "C" void kernel_launch(void* const* d_in, const int* in_sizes, int n_in,
                              void* d_out, int out_size)
{
    const float* k    = (const float*)d_in[0];
    const float* v    = (const float*)d_in[1];
    const float* q    = (const float*)d_in[2];
    const int*   mask = (const int*)d_in[3];
    const float* bias = (const float*)d_in[4];
    const float* Wq   = (const float*)d_in[5];
    const float* bq   = (const float*)d_in[6];
    const float* Wk   = (const float*)d_in[7];
    const float* bk   = (const float*)d_in[8];
    const float* Wv   = (const float*)d_in[9];
    const float* bv   = (const float*)d_in[10];
    const float* Wo   = (const float*)d_in[11];
    const float* bo   = (const float*)d_in[12];
    float* out = (float*)d_out;

    float *pQ, *pK, *pV, *pC;
    cudaGetSymbolAddress((void**)&pQ, g_Q);
    cudaGetSymbolAddress((void**)&pK, g_K);
    cudaGetSymbolAddress((void**)&pV, g_V);
    cudaGetSymbolAddress((void**)&pC, g_CTX);

    const int gemm_smem = (2 * 128 * SA + 2 * 32 * SB) * 4;        // 71680 B
    const int attn_smem = (128 + 3 * 64) * SKV * 4 + 128 * 2 * 4;  // 88064 B
    cudaFuncSetAttribute(gemm_qkv_kernel,
                         cudaFuncAttributeMaxDynamicSharedMemorySize, gemm_smem);
    cudaFuncSetAttribute(gemm_tf32_kernel,
                         cudaFuncAttributeMaxDynamicSharedMemorySize, gemm_smem);
    cudaFuncSetAttribute(flash_tf32_kernel,
                         cudaFuncAttributeMaxDynamicSharedMemorySize, attn_smem);

    const int M = BATCH * SEQ;                    // 4096
    dim3 qkv_grid(DMODEL / 128, M / 128, 3);      // (4, 32, 3) fused QKV
    dim3 gemm_grid(DMODEL / 128, M / 128);        // (4, 32)

    gemm_qkv_kernel<<<qkv_grid, 256, gemm_smem>>>(q, k, v, Wq, Wk, Wv,
                                                  bq, bk, bv, pQ, pK, pV);

    dim3 attn_grid(BATCH, SEQ / 128, NHEADS);     // batch fastest -> bias L2 reuse
    flash_tf32_kernel<<<attn_grid, 256, attn_smem>>>(mask, bias);

    gemm_tf32_kernel<<<gemm_grid, 256, gemm_smem>>>(pC, Wo, bo, out, M, DMODEL, DMODEL, 1.0f);
}

// round 14
// speedup vs baseline: 1.0555x; 1.0239x over previous
#include <cuda_runtime.h>
#include <math_constants.h>
#include <cstdint>

#define SEQ    2048
#define BATCH  2
#define NHEADS 8
#define DMODEL 512
#define HDIM   64

// Scratch (allocation-free): 4 x 8MB
__device__ float g_Q[BATCH * SEQ * DMODEL];
__device__ float g_K[BATCH * SEQ * DMODEL];
__device__ float g_V[BATCH * SEQ * DMODEL];
__device__ float g_CTX[BATCH * SEQ * DMODEL];

// ---------------------------------------------------------------------------
// helpers
// ---------------------------------------------------------------------------
__device__ __forceinline__ float tf32hi(float x) {
    uint32_t u;
    asm("cvt.rna.tf32.f32 %0, %1;" : "=r"(u) : "f"(x));
    return __uint_as_float(u);
}
__device__ __forceinline__ uint32_t tf32u(float x) {
    uint32_t u;
    asm("cvt.rna.tf32.f32 %0, %1;" : "=r"(u) : "f"(x));
    return u;
}

// D += A * B  (m16n8k8, row.col, tf32 in / f32 accum)
__device__ __forceinline__ void mma8(float* c, const uint32_t* a, const uint32_t* b) {
    asm volatile(
        "mma.sync.aligned.m16n8k8.row.col.f32.tf32.tf32.f32 "
        "{%0,%1,%2,%3}, {%4,%5,%6,%7}, {%8,%9}, {%0,%1,%2,%3};"
        : "+f"(c[0]), "+f"(c[1]), "+f"(c[2]), "+f"(c[3])
        : "r"(a[0]), "r"(a[1]), "r"(a[2]), "r"(a[3]), "r"(b[0]), "r"(b[1]));
}

__device__ __forceinline__ void cp_async16(uint32_t dst, const void* src) {
    asm volatile("cp.async.cg.shared.global [%0], [%1], 16;" :: "r"(dst), "l"(src));
}
#define CP_COMMIT() asm volatile("cp.async.commit_group;")
#define CP_WAIT(n)  asm volatile("cp.async.wait_group %0;" :: "n"(n))
__device__ __forceinline__ void l2_prefetch(const void* p) {
    asm volatile("prefetch.global.L2 [%0];" :: "l"(p));
}

// ---------------------------------------------------------------------------
// 3xTF32 GEMM body: Y = (X @ W + bias) * scale.
// 128x128 tile, BK=32, 256 threads = 8 warps (4m x 2n), warp tile 32x64.
// ---------------------------------------------------------------------------
#define SA 36
#define SB 136

__device__ __forceinline__ void gemm_body(
    const float* __restrict__ X, const float* __restrict__ W,
    const float* __restrict__ bias, float* __restrict__ Y,
    int M, int N, int K, float scale, float* sm, int bm, int bn)
{
    float* Ah = sm;
    float* Al = sm + 128 * SA;
    float* Bh = sm + 2 * 128 * SA;
    float* Bl = sm + 2 * 128 * SA + 32 * SB;

    const int tid  = threadIdx.x;
    const int warp = tid >> 5;
    const int lane = tid & 31;
    const int g    = lane >> 2;
    const int tig  = lane & 3;
    const int wm   = warp >> 1;
    const int wn   = warp & 1;

    float C[2][8][4];
#pragma unroll
    for (int s = 0; s < 2; s++)
#pragma unroll
        for (int n = 0; n < 8; n++)
#pragma unroll
            for (int j = 0; j < 4; j++) C[s][n][j] = 0.f;

    for (int k0 = 0; k0 < K; k0 += 32) {
#pragma unroll
        for (int it = 0; it < 4; it++) {
            int idx = tid + it * 256;
            int r   = idx >> 3;
            int c4  = (idx & 7) << 2;
            float4 v = *(const float4*)&X[(size_t)(bm + r) * K + k0 + c4];
            float4 h, l;
            h.x = tf32hi(v.x); l.x = v.x - h.x;
            h.y = tf32hi(v.y); l.y = v.y - h.y;
            h.z = tf32hi(v.z); l.z = v.z - h.z;
            h.w = tf32hi(v.w); l.w = v.w - h.w;
            *(float4*)&Ah[r * SA + c4] = h;
            *(float4*)&Al[r * SA + c4] = l;
        }
#pragma unroll
        for (int it = 0; it < 4; it++) {
            int idx = tid + it * 256;
            int r   = idx >> 5;
            int c4  = (idx & 31) << 2;
            float4 v = *(const float4*)&W[(size_t)(k0 + r) * N + bn + c4];
            float4 h, l;
            h.x = tf32hi(v.x); l.x = v.x - h.x;
            h.y = tf32hi(v.y); l.y = v.y - h.y;
            h.z = tf32hi(v.z); l.z = v.z - h.z;
            h.w = tf32hi(v.w); l.w = v.w - h.w;
            *(float4*)&Bh[r * SB + c4] = h;
            *(float4*)&Bl[r * SB + c4] = l;
        }
        __syncthreads();

#pragma unroll
        for (int kc = 0; kc < 4; kc++) {
            uint32_t ah[2][4], al[2][4];
#pragma unroll
            for (int s = 0; s < 2; s++) {
                int row = wm * 32 + s * 16 + g;
                int dc  = kc * 8 + tig;
                ah[s][0] = __float_as_uint(Ah[row * SA + dc]);
                ah[s][1] = __float_as_uint(Ah[(row + 8) * SA + dc]);
                ah[s][2] = __float_as_uint(Ah[row * SA + dc + 4]);
                ah[s][3] = __float_as_uint(Ah[(row + 8) * SA + dc + 4]);
                al[s][0] = __float_as_uint(Al[row * SA + dc]);
                al[s][1] = __float_as_uint(Al[(row + 8) * SA + dc]);
                al[s][2] = __float_as_uint(Al[row * SA + dc + 4]);
                al[s][3] = __float_as_uint(Al[(row + 8) * SA + dc + 4]);
            }
#pragma unroll
            for (int n = 0; n < 8; n++) {
                int col = wn * 64 + n * 8 + g;
                uint32_t bh[2], bl[2];
                bh[0] = __float_as_uint(Bh[(kc * 8 + tig) * SB + col]);
                bh[1] = __float_as_uint(Bh[(kc * 8 + tig + 4) * SB + col]);
                bl[0] = __float_as_uint(Bl[(kc * 8 + tig) * SB + col]);
                bl[1] = __float_as_uint(Bl[(kc * 8 + tig + 4) * SB + col]);
#pragma unroll
                for (int s = 0; s < 2; s++) {
                    mma8(C[s][n], ah[s], bh);
                    mma8(C[s][n], ah[s], bl);
                    mma8(C[s][n], al[s], bh);
                }
            }
        }
        __syncthreads();
    }

#pragma unroll
    for (int s = 0; s < 2; s++) {
#pragma unroll
        for (int n = 0; n < 8; n++) {
            int row = bm + wm * 32 + s * 16 + g;
            int col = bn + wn * 64 + n * 8 + 2 * tig;
            float b0 = bias[col], b1 = bias[col + 1];
            float2 o;
            o.x = (C[s][n][0] + b0) * scale;
            o.y = (C[s][n][1] + b1) * scale;
            *(float2*)&Y[(size_t)row * N + col] = o;
            o.x = (C[s][n][2] + b0) * scale;
            o.y = (C[s][n][3] + b1) * scale;
            *(float2*)&Y[(size_t)(row + 8) * N + col] = o;
        }
    }
}

// Fused Q/K/V projections: blockIdx.z selects which projection.
__global__ __launch_bounds__(256) void gemm_qkv_kernel(
    const float* __restrict__ q, const float* __restrict__ k, const float* __restrict__ v,
    const float* __restrict__ Wq, const float* __restrict__ Wk, const float* __restrict__ Wv,
    const float* __restrict__ bq, const float* __restrict__ bk, const float* __restrict__ bv,
    float* __restrict__ pQ, float* __restrict__ pK, float* __restrict__ pV)
{
    extern __shared__ float sm[];
    const float *X, *W, *B;
    float* Y;
    float scale;
    if (blockIdx.z == 0)      { X = q; W = Wq; B = bq; Y = pQ; scale = 0.125f; }
    else if (blockIdx.z == 1) { X = k; W = Wk; B = bk; Y = pK; scale = 1.0f; }
    else                      { X = v; W = Wv; B = bv; Y = pV; scale = 1.0f; }
    gemm_body(X, W, B, Y, BATCH * SEQ, DMODEL, DMODEL, scale, sm,
              blockIdx.y * 128, blockIdx.x * 128);
}

// Single GEMM (output projection).
__global__ __launch_bounds__(256) void gemm_tf32_kernel(
    const float* __restrict__ X, const float* __restrict__ W,
    const float* __restrict__ bias, float* __restrict__ Y,
    int M, int N, int K, float scale)
{
    extern __shared__ float sm[];
    gemm_body(X, W, bias, Y, M, N, K, scale, sm, blockIdx.y * 128, blockIdx.x * 128);
}

// ---------------------------------------------------------------------------
// Flash attention: cp.async double-buffered K/V, raw staging, hi/lo at consume.
// CTA = 128 q-rows, one (b,h). 8 warps x 16 rows. 2 CTAs/SM.
// QK: Q rounded tf32 x K hi/lo (2 mmas);  PV: P hi/lo x V rounded (2 mmas).
// Bias/mask: direct gmem loads (R9-proven) + L2 prefetch issued before QK MMAs.
// Smem (floats): Qraw[128*68]=8704 | Kbuf0,Kbuf1[64*68] | Vbuf0,Vbuf1[64*68]
//                total 26112 fl = 104448 B  (<= 113KB -> 2 CTAs/SM)
// ---------------------------------------------------------------------------
#define SKV 68
#define QRAW_FL  (128 * SKV)       // 8704
#define TILE_FL  (64 * SKV)        // 4352

__global__ __launch_bounds__(256, 2) void flash_tf32_kernel(
    const int* __restrict__ mask,
    const float* __restrict__ bias)
{
    extern __shared__ float sm[];
    float* Qraw = sm;

    const int b    = blockIdx.x;
    const int q0   = blockIdx.y * 128;
    const int h    = blockIdx.z;
    const int tid  = threadIdx.x;
    const int warp = tid >> 5;
    const int lane = tid & 31;
    const int g    = lane >> 2;
    const int tig  = lane & 3;

    const float* Qg = g_Q + (size_t)b * SEQ * DMODEL + (size_t)h * HDIM;
    const float* Kg = g_K + (size_t)b * SEQ * DMODEL + (size_t)h * HDIM;
    const float* Vg = g_V + (size_t)b * SEQ * DMODEL + (size_t)h * HDIM;
    const float* biasH = bias + (size_t)h * SEQ * SEQ;

    // per-thread staging coords (64 rows x 16 float4 per tile buffer)
    const int sr = tid >> 4;            // 0..15 (row base, step 16 over 4 iters? no:)
    // each iteration it: idx = tid + it*256 -> r = idx>>4 (0..63), c4 = (idx&15)<<2

    // ---- issue tile 0 K/V cp.async, then stage Q while it flies ----
    {
        float* Kd = sm + QRAW_FL;               // stage 0
        float* Vd = sm + QRAW_FL + 2 * TILE_FL;
#pragma unroll
        for (int it = 0; it < 4; it++) {
            int idx = tid + it * 256;
            int r   = idx >> 4;
            int c4  = (idx & 15) << 2;
            uint32_t kd = (uint32_t)__cvta_generic_to_shared(Kd + r * SKV + c4);
            uint32_t vd = (uint32_t)__cvta_generic_to_shared(Vd + r * SKV + c4);
            cp_async16(kd, Kg + (size_t)r * DMODEL + c4);
            cp_async16(vd, Vg + (size_t)r * DMODEL + c4);
        }
        CP_COMMIT();
    }
#pragma unroll
    for (int it = 0; it < 8; it++) {
        int idx = tid + it * 256;          // 0..2047
        int r   = idx >> 4;
        int c4  = (idx & 15) << 2;
        *(float4*)&Qraw[r * SKV + c4] =
            *(const float4*)&Qg[(size_t)(q0 + r) * DMODEL + c4];
    }

    float O[8][4];
#pragma unroll
    for (int n = 0; n < 8; n++)
#pragma unroll
        for (int j = 0; j < 4; j++) O[n][j] = 0.f;
    float m0 = -CUDART_INF_F, m1 = -CUDART_INF_F, l0 = 0.f, l1 = 0.f;

    const int r1   = warp * 16 + g;        // CTA-local q-rows
    const int r2   = r1 + 8;
    const int row0 = q0 + r1;              // global q-rows
    const int row1 = row0 + 8;

    for (int t = 0; t < SEQ / 64; t++) {
        const int k0 = t * 64;
        const int s  = t & 1;
        float* Kr = sm + QRAW_FL + s * TILE_FL;
        float* Vr = sm + QRAW_FL + 2 * TILE_FL + s * TILE_FL;

        // ---- issue next tile's cp.async into the other buffer ----
        if (t + 1 < SEQ / 64) {
            float* Kd = sm + QRAW_FL + (s ^ 1) * TILE_FL;
            float* Vd = sm + QRAW_FL + 2 * TILE_FL + (s ^ 1) * TILE_FL;
            const float* Ksrc = Kg + (size_t)(k0 + 64) * DMODEL;
            const float* Vsrc = Vg + (size_t)(k0 + 64) * DMODEL;
#pragma unroll
            for (int it = 0; it < 4; it++) {
                int idx = tid + it * 256;
                int r   = idx >> 4;
                int c4  = (idx & 15) << 2;
                uint32_t kd = (uint32_t)__cvta_generic_to_shared(Kd + r * SKV + c4);
                uint32_t vd = (uint32_t)__cvta_generic_to_shared(Vd + r * SKV + c4);
                cp_async16(kd, Ksrc + (size_t)r * DMODEL + c4);
                cp_async16(vd, Vsrc + (size_t)r * DMODEL + c4);
            }
            CP_COMMIT();
            CP_WAIT(1);        // tile t's group complete
        } else {
            CP_WAIT(0);
        }
        __syncthreads();

        // ---- L2 prefetch for this tile's bias+mask (consumed after 128 MMAs) ----
        {
            const float* bp0 = &biasH[(size_t)row0 * SEQ + k0];
            const float* bp1 = &biasH[(size_t)row1 * SEQ + k0];
            const int*   mp0 = &mask [(size_t)row0 * SEQ + k0];
            const int*   mp1 = &mask [(size_t)row1 * SEQ + k0];
            l2_prefetch(bp0); l2_prefetch(bp0 + 32);
            l2_prefetch(bp1); l2_prefetch(bp1 + 32);
            l2_prefetch(mp0); l2_prefetch(mp0 + 32);
            l2_prefetch(mp1); l2_prefetch(mp1 + 32);
        }

        // ---- S = Q @ K^T (Q rounded x K hi/lo-at-consume) ----
        float S[8][4];
#pragma unroll
        for (int n = 0; n < 8; n++)
            S[n][0] = S[n][1] = S[n][2] = S[n][3] = 0.f;

#pragma unroll
        for (int c = 0; c < 8; c++) {
            int dc = c * 8 + tig;
            uint32_t a[4];
            a[0] = tf32u(Qraw[r1 * SKV + dc]);
            a[1] = tf32u(Qraw[r2 * SKV + dc]);
            a[2] = tf32u(Qraw[r1 * SKV + dc + 4]);
            a[3] = tf32u(Qraw[r2 * SKV + dc + 4]);
#pragma unroll
            for (int n = 0; n < 8; n++) {
                int krow = n * 8 + g;
                float k0f = Kr[krow * SKV + dc];
                float k1f = Kr[krow * SKV + dc + 4];
                uint32_t bh[2], bl[2];
                bh[0] = tf32u(k0f);
                bh[1] = tf32u(k1f);
                bl[0] = __float_as_uint(k0f - __uint_as_float(bh[0]));
                bl[1] = __float_as_uint(k1f - __uint_as_float(bh[1]));
                mma8(S[n], a, bh);
                mma8(S[n], a, bl);
            }
        }

        // ---- bias + mask (direct loads; latency covered by prefetch + MMAs) ----
#pragma unroll
        for (int n = 0; n < 8; n++) {
            int col = k0 + n * 8 + 2 * tig;
            float2 bv0 = *(const float2*)&biasH[(size_t)row0 * SEQ + col];
            int2   mv0 = *(const int2*)  &mask [(size_t)row0 * SEQ + col];
            float2 bv1 = *(const float2*)&biasH[(size_t)row1 * SEQ + col];
            int2   mv1 = *(const int2*)  &mask [(size_t)row1 * SEQ + col];
            S[n][0] = mv0.x ? S[n][0] + bv0.x : -CUDART_INF_F;
            S[n][1] = mv0.y ? S[n][1] + bv0.y : -CUDART_INF_F;
            S[n][2] = mv1.x ? S[n][2] + bv1.x : -CUDART_INF_F;
            S[n][3] = mv1.y ? S[n][3] + bv1.y : -CUDART_INF_F;
        }

        // ---- online softmax (rows g / g+8, quad-wide reductions) ----
        float mx0 = -CUDART_INF_F, mx1 = -CUDART_INF_F;
#pragma unroll
        for (int n = 0; n < 8; n++) {
            mx0 = fmaxf(mx0, fmaxf(S[n][0], S[n][1]));
            mx1 = fmaxf(mx1, fmaxf(S[n][2], S[n][3]));
        }
        mx0 = fmaxf(mx0, __shfl_xor_sync(0xffffffffu, mx0, 1));
        mx0 = fmaxf(mx0, __shfl_xor_sync(0xffffffffu, mx0, 2));
        mx1 = fmaxf(mx1, __shfl_xor_sync(0xffffffffu, mx1, 1));
        mx1 = fmaxf(mx1, __shfl_xor_sync(0xffffffffu, mx1, 2));

        float mn0 = fmaxf(m0, mx0), mn1 = fmaxf(m1, mx1);
        float ref0 = (mn0 == -CUDART_INF_F) ? 0.f : mn0;
        float ref1 = (mn1 == -CUDART_INF_F) ? 0.f : mn1;
        float alpha0 = __expf(m0 - ref0);
        float alpha1 = __expf(m1 - ref1);
        m0 = mn0; m1 = mn1;

        float rs0 = 0.f, rs1 = 0.f;
#pragma unroll
        for (int n = 0; n < 8; n++) {
            S[n][0] = __expf(S[n][0] - ref0);
            S[n][1] = __expf(S[n][1] - ref0);
            S[n][2] = __expf(S[n][2] - ref1);
            S[n][3] = __expf(S[n][3] - ref1);
            rs0 += S[n][0] + S[n][1];
            rs1 += S[n][2] + S[n][3];
        }
        rs0 += __shfl_xor_sync(0xffffffffu, rs0, 1);
        rs0 += __shfl_xor_sync(0xffffffffu, rs0, 2);
        rs1 += __shfl_xor_sync(0xffffffffu, rs1, 1);
        rs1 += __shfl_xor_sync(0xffffffffu, rs1, 2);
        l0 = l0 * alpha0 + rs0;
        l1 = l1 * alpha1 + rs1;

#pragma unroll
        for (int n = 0; n < 8; n++) {
            O[n][0] *= alpha0; O[n][1] *= alpha0;
            O[n][2] *= alpha1; O[n][3] *= alpha1;
        }

        // ---- O += P @ V (P hi/lo x V rounded-at-consume). A-frags via shuffles ----
        const int srcA = (g << 2) | (tig >> 1);
        const int srcB = srcA + 2;
        const bool sel = tig & 1;
#pragma unroll
        for (int c = 0; c < 8; c++) {
            float vA0 = __shfl_sync(0xffffffffu, S[c][0], srcA);
            float vA1 = __shfl_sync(0xffffffffu, S[c][1], srcA);
            float vA2 = __shfl_sync(0xffffffffu, S[c][2], srcA);
            float vA3 = __shfl_sync(0xffffffffu, S[c][3], srcA);
            float vB0 = __shfl_sync(0xffffffffu, S[c][0], srcB);
            float vB1 = __shfl_sync(0xffffffffu, S[c][1], srcB);
            float vB2 = __shfl_sync(0xffffffffu, S[c][2], srcB);
            float vB3 = __shfl_sync(0xffffffffu, S[c][3], srcB);
            float pa0 = sel ? vA1 : vA0;   // (row g,   key c*8+tig)
            float pa1 = sel ? vA3 : vA2;   // (row g+8, key c*8+tig)
            float pa2 = sel ? vB1 : vB0;   // (row g,   key c*8+tig+4)
            float pa3 = sel ? vB3 : vB2;   // (row g+8, key c*8+tig+4)
            uint32_t pah[4], pal[4];
            float h0 = tf32hi(pa0), h1 = tf32hi(pa1), h2 = tf32hi(pa2), h3 = tf32hi(pa3);
            pah[0] = __float_as_uint(h0); pal[0] = __float_as_uint(pa0 - h0);
            pah[1] = __float_as_uint(h1); pal[1] = __float_as_uint(pa1 - h1);
            pah[2] = __float_as_uint(h2); pal[2] = __float_as_uint(pa2 - h2);
            pah[3] = __float_as_uint(h3); pal[3] = __float_as_uint(pa3 - h3);

            int vrow = c * 8 + tig;   // key
#pragma unroll
            for (int n = 0; n < 8; n++) {
                int vcol = n * 8 + g; // d
                uint32_t bh[2];
                bh[0] = tf32u(Vr[vrow * SKV + vcol]);
                bh[1] = tf32u(Vr[(vrow + 4) * SKV + vcol]);
                mma8(O[n], pah, bh);
                mma8(O[n], pal, bh);
            }
        }
        __syncthreads();   // all reads of buf s done before t+2 stages into it
    }

    // ---- epilogue: normalize, write ctx [b, s, h*64+d] ----
    float inv0 = (l0 > 0.f) ? (1.f / l0) : 0.f;
    float inv1 = (l1 > 0.f) ? (1.f / l1) : 0.f;
#pragma unroll
    for (int n = 0; n < 8; n++) {
        int col = h * HDIM + n * 8 + 2 * tig;
        float2 o;
        o.x = O[n][0] * inv0; o.y = O[n][1] * inv0;
        *(float2*)&g_CTX[(size_t)(b * SEQ + row0) * DMODEL + col] = o;
        o.x = O[n][2] * inv1; o.y = O[n][3] * inv1;
        *(float2*)&g_CTX[(size_t)(b * SEQ + row1) * DMODEL + col] = o;
    }
}

// ---------------------------------------------------------------------------
// Launch
// ---------------------------------------------------------------------------
extern "C" void kernel_launch(void* const* d_in, const int* in_sizes, int n_in,
                              void* d_out, int out_size)
{
    const float* k    = (const float*)d_in[0];
    const float* v    = (const float*)d_in[1];
    const float* q    = (const float*)d_in[2];
    const int*   mask = (const int*)d_in[3];
    const float* bias = (const float*)d_in[4];
    const float* Wq   = (const float*)d_in[5];
    const float* bq   = (const float*)d_in[6];
    const float* Wk   = (const float*)d_in[7];
    const float* bk   = (const float*)d_in[8];
    const float* Wv   = (const float*)d_in[9];
    const float* bv   = (const float*)d_in[10];
    const float* Wo   = (const float*)d_in[11];
    const float* bo   = (const float*)d_in[12];
    float* out = (float*)d_out;

    float *pQ, *pK, *pV, *pC;
    cudaGetSymbolAddress((void**)&pQ, g_Q);
    cudaGetSymbolAddress((void**)&pK, g_K);
    cudaGetSymbolAddress((void**)&pV, g_V);
    cudaGetSymbolAddress((void**)&pC, g_CTX);

    const int gemm_smem = (2 * 128 * SA + 2 * 32 * SB) * 4;    // 71680 B
    const int attn_smem = (QRAW_FL + 4 * TILE_FL) * 4;          // 104448 B
    cudaFuncSetAttribute(gemm_qkv_kernel,
                         cudaFuncAttributeMaxDynamicSharedMemorySize, gemm_smem);
    cudaFuncSetAttribute(gemm_tf32_kernel,
                         cudaFuncAttributeMaxDynamicSharedMemorySize, gemm_smem);
    cudaFuncSetAttribute(flash_tf32_kernel,
                         cudaFuncAttributeMaxDynamicSharedMemorySize, attn_smem);

    const int M = BATCH * SEQ;                    // 4096
    dim3 qkv_grid(DMODEL / 128, M / 128, 3);      // (4, 32, 3) fused QKV
    dim3 gemm_grid(DMODEL / 128, M / 128);        // (4, 32)

    gemm_qkv_kernel<<<qkv_grid, 256, gemm_smem>>>(q, k, v, Wq, Wk, Wv,
                                                  bq, bk, bv, pQ, pK, pV);

    dim3 attn_grid(BATCH, SEQ / 128, NHEADS);     // batch fastest -> bias L2 reuse
    flash_tf32_kernel<<<attn_grid, 256, attn_smem>>>(mask, bias);

    gemm_tf32_kernel<<<gemm_grid, 256, gemm_smem>>>(pC, Wo, bo, out, M, DMODEL, DMODEL, 1.0f);
}

// round 16
// speedup vs baseline: 1.2247x; 1.1602x over previous
#include <cuda_runtime.h>
#include <math_constants.h>
#include <cstdint>

#define SEQ    2048
#define BATCH  2
#define NHEADS 8
#define DMODEL 512
#define HDIM   64

// Scratch (allocation-free): 4 x 8MB
__device__ float g_Q[BATCH * SEQ * DMODEL];
__device__ float g_K[BATCH * SEQ * DMODEL];
__device__ float g_V[BATCH * SEQ * DMODEL];
__device__ float g_CTX[BATCH * SEQ * DMODEL];

// ---------------------------------------------------------------------------
// helpers
// ---------------------------------------------------------------------------
__device__ __forceinline__ float tf32hi(float x) {
    uint32_t u;
    asm("cvt.rna.tf32.f32 %0, %1;" : "=r"(u) : "f"(x));
    return __uint_as_float(u);
}

// D += A * B  (m16n8k8, row.col, tf32 in / f32 accum) -- GEMMs only
__device__ __forceinline__ void mma8(float* c, const uint32_t* a, const uint32_t* b) {
    asm volatile(
        "mma.sync.aligned.m16n8k8.row.col.f32.tf32.tf32.f32 "
        "{%0,%1,%2,%3}, {%4,%5,%6,%7}, {%8,%9}, {%0,%1,%2,%3};"
        : "+f"(c[0]), "+f"(c[1]), "+f"(c[2]), "+f"(c[3])
        : "r"(a[0]), "r"(a[1]), "r"(a[2]), "r"(a[3]), "r"(b[0]), "r"(b[1]));
}

// D += A * B  (m16n8k16, row.col, bf16 in / f32 accum) -- flash
__device__ __forceinline__ void mma16(float* c, const uint32_t* a, const uint32_t* b) {
    asm volatile(
        "mma.sync.aligned.m16n8k16.row.col.f32.bf16.bf16.f32 "
        "{%0,%1,%2,%3}, {%4,%5,%6,%7}, {%8,%9}, {%0,%1,%2,%3};"
        : "+f"(c[0]), "+f"(c[1]), "+f"(c[2]), "+f"(c[3])
        : "r"(a[0]), "r"(a[1]), "r"(a[2]), "r"(a[3]), "r"(b[0]), "r"(b[1]));
}

// Split (x, y) into bf16x2 hi word (lo-half = x, hi-half = y) + bf16x2 lo word.
__device__ __forceinline__ void bf16_split2(float x, float y, uint32_t& hi, uint32_t& lo) {
    asm("cvt.rn.bf16x2.f32 %0, %1, %2;" : "=r"(hi) : "f"(y), "f"(x));
    float xh = __uint_as_float(hi << 16);
    float yh = __uint_as_float(hi & 0xFFFF0000u);
    float xl = x - xh;
    float yl = y - yh;
    asm("cvt.rn.bf16x2.f32 %0, %1, %2;" : "=r"(lo) : "f"(yl), "f"(xl));
}

__device__ __forceinline__ void l2_prefetch(const void* p) {
    asm volatile("prefetch.global.L2 [%0];" :: "l"(p));
}

// ---------------------------------------------------------------------------
// 3xTF32 GEMM body (unchanged): Y = (X @ W + bias) * scale.
// ---------------------------------------------------------------------------
#define SA 36
#define SB 136

__device__ __forceinline__ void gemm_body(
    const float* __restrict__ X, const float* __restrict__ W,
    const float* __restrict__ bias, float* __restrict__ Y,
    int M, int N, int K, float scale, float* sm, int bm, int bn)
{
    float* Ah = sm;
    float* Al = sm + 128 * SA;
    float* Bh = sm + 2 * 128 * SA;
    float* Bl = sm + 2 * 128 * SA + 32 * SB;

    const int tid  = threadIdx.x;
    const int warp = tid >> 5;
    const int lane = tid & 31;
    const int g    = lane >> 2;
    const int tig  = lane & 3;
    const int wm   = warp >> 1;
    const int wn   = warp & 1;

    float C[2][8][4];
#pragma unroll
    for (int s = 0; s < 2; s++)
#pragma unroll
        for (int n = 0; n < 8; n++)
#pragma unroll
            for (int j = 0; j < 4; j++) C[s][n][j] = 0.f;

    for (int k0 = 0; k0 < K; k0 += 32) {
#pragma unroll
        for (int it = 0; it < 4; it++) {
            int idx = tid + it * 256;
            int r   = idx >> 3;
            int c4  = (idx & 7) << 2;
            float4 v = *(const float4*)&X[(size_t)(bm + r) * K + k0 + c4];
            float4 h, l;
            h.x = tf32hi(v.x); l.x = v.x - h.x;
            h.y = tf32hi(v.y); l.y = v.y - h.y;
            h.z = tf32hi(v.z); l.z = v.z - h.z;
            h.w = tf32hi(v.w); l.w = v.w - h.w;
            *(float4*)&Ah[r * SA + c4] = h;
            *(float4*)&Al[r * SA + c4] = l;
        }
#pragma unroll
        for (int it = 0; it < 4; it++) {
            int idx = tid + it * 256;
            int r   = idx >> 5;
            int c4  = (idx & 31) << 2;
            float4 v = *(const float4*)&W[(size_t)(k0 + r) * N + bn + c4];
            float4 h, l;
            h.x = tf32hi(v.x); l.x = v.x - h.x;
            h.y = tf32hi(v.y); l.y = v.y - h.y;
            h.z = tf32hi(v.z); l.z = v.z - h.z;
            h.w = tf32hi(v.w); l.w = v.w - h.w;
            *(float4*)&Bh[r * SB + c4] = h;
            *(float4*)&Bl[r * SB + c4] = l;
        }
        __syncthreads();

#pragma unroll
        for (int kc = 0; kc < 4; kc++) {
            uint32_t ah[2][4], al[2][4];
#pragma unroll
            for (int s = 0; s < 2; s++) {
                int row = wm * 32 + s * 16 + g;
                int dc  = kc * 8 + tig;
                ah[s][0] = __float_as_uint(Ah[row * SA + dc]);
                ah[s][1] = __float_as_uint(Ah[(row + 8) * SA + dc]);
                ah[s][2] = __float_as_uint(Ah[row * SA + dc + 4]);
                ah[s][3] = __float_as_uint(Ah[(row + 8) * SA + dc + 4]);
                al[s][0] = __float_as_uint(Al[row * SA + dc]);
                al[s][1] = __float_as_uint(Al[(row + 8) * SA + dc]);
                al[s][2] = __float_as_uint(Al[row * SA + dc + 4]);
                al[s][3] = __float_as_uint(Al[(row + 8) * SA + dc + 4]);
            }
#pragma unroll
            for (int n = 0; n < 8; n++) {
                int col = wn * 64 + n * 8 + g;
                uint32_t bh[2], bl[2];
                bh[0] = __float_as_uint(Bh[(kc * 8 + tig) * SB + col]);
                bh[1] = __float_as_uint(Bh[(kc * 8 + tig + 4) * SB + col]);
                bl[0] = __float_as_uint(Bl[(kc * 8 + tig) * SB + col]);
                bl[1] = __float_as_uint(Bl[(kc * 8 + tig + 4) * SB + col]);
#pragma unroll
                for (int s = 0; s < 2; s++) {
                    mma8(C[s][n], ah[s], bh);
                    mma8(C[s][n], ah[s], bl);
                    mma8(C[s][n], al[s], bh);
                }
            }
        }
        __syncthreads();
    }

#pragma unroll
    for (int s = 0; s < 2; s++) {
#pragma unroll
        for (int n = 0; n < 8; n++) {
            int row = bm + wm * 32 + s * 16 + g;
            int col = bn + wn * 64 + n * 8 + 2 * tig;
            float b0 = bias[col], b1 = bias[col + 1];
            float2 o;
            o.x = (C[s][n][0] + b0) * scale;
            o.y = (C[s][n][1] + b1) * scale;
            *(float2*)&Y[(size_t)row * N + col] = o;
            o.x = (C[s][n][2] + b0) * scale;
            o.y = (C[s][n][3] + b1) * scale;
            *(float2*)&Y[(size_t)(row + 8) * N + col] = o;
        }
    }
}

__global__ __launch_bounds__(256) void gemm_qkv_kernel(
    const float* __restrict__ q, const float* __restrict__ k, const float* __restrict__ v,
    const float* __restrict__ Wq, const float* __restrict__ Wk, const float* __restrict__ Wv,
    const float* __restrict__ bq, const float* __restrict__ bk, const float* __restrict__ bv,
    float* __restrict__ pQ, float* __restrict__ pK, float* __restrict__ pV)
{
    extern __shared__ float sm[];
    const float *X, *W, *B;
    float* Y;
    float scale;
    if (blockIdx.z == 0)      { X = q; W = Wq; B = bq; Y = pQ; scale = 0.125f; }
    else if (blockIdx.z == 1) { X = k; W = Wk; B = bk; Y = pK; scale = 1.0f; }
    else                      { X = v; W = Wv; B = bv; Y = pV; scale = 1.0f; }
    gemm_body(X, W, B, Y, BATCH * SEQ, DMODEL, DMODEL, scale, sm,
              blockIdx.y * 128, blockIdx.x * 128);
}

__global__ __launch_bounds__(256) void gemm_tf32_kernel(
    const float* __restrict__ X, const float* __restrict__ W,
    const float* __restrict__ bias, float* __restrict__ Y,
    int M, int N, int K, float scale)
{
    extern __shared__ float sm[];
    gemm_body(X, W, bias, Y, M, N, K, scale, sm, blockIdx.y * 128, blockIdx.x * 128);
}

// ---------------------------------------------------------------------------
// Flash attention, 3xBF16 m16n8k16. CTA = 128 q-rows, one (b,h). 8 warps. 2 CTAs/SM.
// All operands staged in smem as packed bf16x2 hi/lo words:
//   Qbf[qrow][dp]  (dp = d/2, pair (2dp,2dp+1)), stride SQW=36 -> frag LDS conflict-free
//   Kbf[key][dp]   stride SKW=36
//   Vbf[kp][d]     (pair = keys (2kp,2kp+1) at col d), stride SVW=72
// QK: 3 mmas (qh*kh, qh*kl, ql*kh); PV: 3 mmas (ph*vh, ph*vl, pl*vh).
// P A-frags come straight from S C-frags via cvt packs -- NO shuffles.
// ---------------------------------------------------------------------------
#define SQW 36
#define SKW 36
#define SVW 72
#define OFF_QH 0
#define OFF_QL (128 * SQW)                   // 4608
#define OFF_KH (2 * 128 * SQW)               // 9216
#define OFF_KL (OFF_KH + 64 * SKW)           // 11520
#define OFF_VH (OFF_KL + 64 * SKW)           // 13824
#define OFF_VL (OFF_VH + 32 * SVW)           // 16128
#define SMW_TOTAL (OFF_VL + 32 * SVW)        // 18432 words = 73728 B

__global__ __launch_bounds__(256, 2) void flash_bf16_kernel(
    const int* __restrict__ mask,
    const float* __restrict__ bias)
{
    extern __shared__ uint32_t smw[];
    uint32_t* QH = smw + OFF_QH;
    uint32_t* QL = smw + OFF_QL;
    uint32_t* KH = smw + OFF_KH;
    uint32_t* KL = smw + OFF_KL;
    uint32_t* VH = smw + OFF_VH;
    uint32_t* VL = smw + OFF_VL;

    const int b    = blockIdx.x;
    const int q0   = blockIdx.y * 128;
    const int h    = blockIdx.z;
    const int tid  = threadIdx.x;
    const int warp = tid >> 5;
    const int lane = tid & 31;
    const int g    = lane >> 2;
    const int tig  = lane & 3;

    const float* Qg = g_Q + (size_t)b * SEQ * DMODEL + (size_t)h * HDIM;
    const float* Kg = g_K + (size_t)b * SEQ * DMODEL + (size_t)h * HDIM;
    const float* Vg = g_V + (size_t)b * SEQ * DMODEL + (size_t)h * HDIM;
    const float* biasH = bias + (size_t)h * SEQ * SEQ;

    // ---- Stage Q once: split to bf16 hi/lo packed words ----
#pragma unroll
    for (int it = 0; it < 8; it++) {
        int idx = tid + it * 256;          // 0..2047  (128 rows x 16 float4)
        int r   = idx >> 4;
        int c4  = (idx & 15) << 2;
        float4 v = *(const float4*)&Qg[(size_t)(q0 + r) * DMODEL + c4];
        uint32_t h0, l0, h1, l1;
        bf16_split2(v.x, v.y, h0, l0);
        bf16_split2(v.z, v.w, h1, l1);
        int w = r * SQW + (c4 >> 1);
        *(uint2*)&QH[w] = make_uint2(h0, h1);
        *(uint2*)&QL[w] = make_uint2(l0, l1);
    }

    float O[8][4];
#pragma unroll
    for (int n = 0; n < 8; n++)
#pragma unroll
        for (int j = 0; j < 4; j++) O[n][j] = 0.f;
    float m0 = -CUDART_INF_F, m1 = -CUDART_INF_F, l0s = 0.f, l1s = 0.f;

    const int r1   = warp * 16 + g;        // CTA-local q-rows
    const int r2   = r1 + 8;
    const int row0 = q0 + r1;              // global q-rows
    const int row1 = row0 + 8;

    for (int k0 = 0; k0 < SEQ; k0 += 64) {
        // ---- Stage K tile (64x64) ----
#pragma unroll
        for (int it = 0; it < 4; it++) {
            int idx = tid + it * 256;       // 0..1023
            int r   = idx >> 4;             // key 0..63
            int c4  = (idx & 15) << 2;
            float4 v = *(const float4*)&Kg[(size_t)(k0 + r) * DMODEL + c4];
            uint32_t h0, l0, h1, l1;
            bf16_split2(v.x, v.y, h0, l0);
            bf16_split2(v.z, v.w, h1, l1);
            int w = r * SKW + (c4 >> 1);
            *(uint2*)&KH[w] = make_uint2(h0, h1);
            *(uint2*)&KL[w] = make_uint2(l0, l1);
        }
        // ---- Stage V tile, transposed-pair packing: word(kp,d)=(V[2kp][d],V[2kp+1][d]) ----
#pragma unroll
        for (int it = 0; it < 2; it++) {
            int idx = tid + it * 256;       // 0..511
            int kp  = idx >> 4;             // 0..31
            int c4  = (idx & 15) << 2;      // d
            float4 va = *(const float4*)&Vg[(size_t)(k0 + 2 * kp) * DMODEL + c4];
            float4 vb = *(const float4*)&Vg[(size_t)(k0 + 2 * kp + 1) * DMODEL + c4];
            uint32_t hw[4], lw[4];
            bf16_split2(va.x, vb.x, hw[0], lw[0]);
            bf16_split2(va.y, vb.y, hw[1], lw[1]);
            bf16_split2(va.z, vb.z, hw[2], lw[2]);
            bf16_split2(va.w, vb.w, hw[3], lw[3]);
            int w = kp * SVW + c4;
            *(uint4*)&VH[w] = make_uint4(hw[0], hw[1], hw[2], hw[3]);
            *(uint4*)&VL[w] = make_uint4(lw[0], lw[1], lw[2], lw[3]);
        }
        __syncthreads();

        // ---- L2 prefetch for this tile's bias+mask ----
        {
            const float* bp0 = &biasH[(size_t)row0 * SEQ + k0];
            const float* bp1 = &biasH[(size_t)row1 * SEQ + k0];
            const int*   mp0 = &mask [(size_t)row0 * SEQ + k0];
            const int*   mp1 = &mask [(size_t)row1 * SEQ + k0];
            l2_prefetch(bp0); l2_prefetch(bp0 + 32);
            l2_prefetch(bp1); l2_prefetch(bp1 + 32);
            l2_prefetch(mp0); l2_prefetch(mp0 + 32);
            l2_prefetch(mp1); l2_prefetch(mp1 + 32);
        }

        // ---- S = Q @ K^T  (3xBF16, chunks of k=16) ----
        float S[8][4];
#pragma unroll
        for (int n = 0; n < 8; n++)
            S[n][0] = S[n][1] = S[n][2] = S[n][3] = 0.f;

#pragma unroll
        for (int c = 0; c < 4; c++) {
            int qa1 = r1 * SQW + 8 * c + tig;
            int qa2 = r2 * SQW + 8 * c + tig;
            uint32_t ah[4], al[4];
            ah[0] = QH[qa1]; ah[1] = QH[qa2]; ah[2] = QH[qa1 + 4]; ah[3] = QH[qa2 + 4];
            al[0] = QL[qa1]; al[1] = QL[qa2]; al[2] = QL[qa1 + 4]; al[3] = QL[qa2 + 4];
#pragma unroll
            for (int n = 0; n < 8; n++) {
                int kb = (n * 8 + g) * SKW + 8 * c + tig;
                uint32_t bh[2], bl[2];
                bh[0] = KH[kb]; bh[1] = KH[kb + 4];
                bl[0] = KL[kb]; bl[1] = KL[kb + 4];
                mma16(S[n], ah, bh);
                mma16(S[n], ah, bl);
                mma16(S[n], al, bh);
            }
        }

        // ---- bias + mask ----
#pragma unroll
        for (int n = 0; n < 8; n++) {
            int col = k0 + n * 8 + 2 * tig;
            float2 bv0 = *(const float2*)&biasH[(size_t)row0 * SEQ + col];
            int2   mv0 = *(const int2*)  &mask [(size_t)row0 * SEQ + col];
            float2 bv1 = *(const float2*)&biasH[(size_t)row1 * SEQ + col];
            int2   mv1 = *(const int2*)  &mask [(size_t)row1 * SEQ + col];
            S[n][0] = mv0.x ? S[n][0] + bv0.x : -CUDART_INF_F;
            S[n][1] = mv0.y ? S[n][1] + bv0.y : -CUDART_INF_F;
            S[n][2] = mv1.x ? S[n][2] + bv1.x : -CUDART_INF_F;
            S[n][3] = mv1.y ? S[n][3] + bv1.y : -CUDART_INF_F;
        }

        // ---- online softmax ----
        float mx0 = -CUDART_INF_F, mx1 = -CUDART_INF_F;
#pragma unroll
        for (int n = 0; n < 8; n++) {
            mx0 = fmaxf(mx0, fmaxf(S[n][0], S[n][1]));
            mx1 = fmaxf(mx1, fmaxf(S[n][2], S[n][3]));
        }
        mx0 = fmaxf(mx0, __shfl_xor_sync(0xffffffffu, mx0, 1));
        mx0 = fmaxf(mx0, __shfl_xor_sync(0xffffffffu, mx0, 2));
        mx1 = fmaxf(mx1, __shfl_xor_sync(0xffffffffu, mx1, 1));
        mx1 = fmaxf(mx1, __shfl_xor_sync(0xffffffffu, mx1, 2));

        float mn0 = fmaxf(m0, mx0), mn1 = fmaxf(m1, mx1);
        float ref0 = (mn0 == -CUDART_INF_F) ? 0.f : mn0;
        float ref1 = (mn1 == -CUDART_INF_F) ? 0.f : mn1;
        float alpha0 = __expf(m0 - ref0);
        float alpha1 = __expf(m1 - ref1);
        m0 = mn0; m1 = mn1;

        float rs0 = 0.f, rs1 = 0.f;
#pragma unroll
        for (int n = 0; n < 8; n++) {
            S[n][0] = __expf(S[n][0] - ref0);
            S[n][1] = __expf(S[n][1] - ref0);
            S[n][2] = __expf(S[n][2] - ref1);
            S[n][3] = __expf(S[n][3] - ref1);
            rs0 += S[n][0] + S[n][1];
            rs1 += S[n][2] + S[n][3];
        }
        rs0 += __shfl_xor_sync(0xffffffffu, rs0, 1);
        rs0 += __shfl_xor_sync(0xffffffffu, rs0, 2);
        rs1 += __shfl_xor_sync(0xffffffffu, rs1, 1);
        rs1 += __shfl_xor_sync(0xffffffffu, rs1, 2);
        l0s = l0s * alpha0 + rs0;
        l1s = l1s * alpha1 + rs1;

#pragma unroll
        for (int n = 0; n < 8; n++) {
            O[n][0] *= alpha0; O[n][1] *= alpha0;
            O[n][2] *= alpha1; O[n][3] *= alpha1;
        }

        // ---- O += P @ V : P A-frags directly from S C-frags (no shuffles) ----
#pragma unroll
        for (int c = 0; c < 4; c++) {
            uint32_t ph[4], pl[4];
            bf16_split2(S[2 * c][0],     S[2 * c][1],     ph[0], pl[0]);
            bf16_split2(S[2 * c][2],     S[2 * c][3],     ph[1], pl[1]);
            bf16_split2(S[2 * c + 1][0], S[2 * c + 1][1], ph[2], pl[2]);
            bf16_split2(S[2 * c + 1][2], S[2 * c + 1][3], ph[3], pl[3]);
#pragma unroll
            for (int n = 0; n < 8; n++) {
                int vb0 = (8 * c + tig) * SVW + n * 8 + g;
                int vb1 = vb0 + 4 * SVW;
                uint32_t vh[2], vl[2];
                vh[0] = VH[vb0]; vh[1] = VH[vb1];
                vl[0] = VL[vb0]; vl[1] = VL[vb1];
                mma16(O[n], ph, vh);
                mma16(O[n], ph, vl);
                mma16(O[n], pl, vh);
            }
        }
        __syncthreads();   // before next tile's staging overwrites K/V
    }

    // ---- epilogue: normalize, write ctx [b, s, h*64+d] ----
    float inv0 = (l0s > 0.f) ? (1.f / l0s) : 0.f;
    float inv1 = (l1s > 0.f) ? (1.f / l1s) : 0.f;
#pragma unroll
    for (int n = 0; n < 8; n++) {
        int col = h * HDIM + n * 8 + 2 * tig;
        float2 o;
        o.x = O[n][0] * inv0; o.y = O[n][1] * inv0;
        *(float2*)&g_CTX[(size_t)(b * SEQ + row0) * DMODEL + col] = o;
        o.x = O[n][2] * inv1; o.y = O[n][3] * inv1;
        *(float2*)&g_CTX[(size_t)(b * SEQ + row1) * DMODEL + col] = o;
    }
}

// ---------------------------------------------------------------------------
// Launch
// ---------------------------------------------------------------------------
extern "C" void kernel_launch(void* const* d_in, const int* in_sizes, int n_in,
                              void* d_out, int out_size)
{
    const float* k    = (const float*)d_in[0];
    const float* v    = (const float*)d_in[1];
    const float* q    = (const float*)d_in[2];
    const int*   mask = (const int*)d_in[3];
    const float* bias = (const float*)d_in[4];
    const float* Wq   = (const float*)d_in[5];
    const float* bq   = (const float*)d_in[6];
    const float* Wk   = (const float*)d_in[7];
    const float* bk   = (const float*)d_in[8];
    const float* Wv   = (const float*)d_in[9];
    const float* bv   = (const float*)d_in[10];
    const float* Wo   = (const float*)d_in[11];
    const float* bo   = (const float*)d_in[12];
    float* out = (float*)d_out;

    float *pQ, *pK, *pV, *pC;
    cudaGetSymbolAddress((void**)&pQ, g_Q);
    cudaGetSymbolAddress((void**)&pK, g_K);
    cudaGetSymbolAddress((void**)&pV, g_V);
    cudaGetSymbolAddress((void**)&pC, g_CTX);

    const int gemm_smem = (2 * 128 * SA + 2 * 32 * SB) * 4;    // 71680 B
    const int attn_smem = SMW_TOTAL * 4;                        // 73728 B
    cudaFuncSetAttribute(gemm_qkv_kernel,
                         cudaFuncAttributeMaxDynamicSharedMemorySize, gemm_smem);
    cudaFuncSetAttribute(gemm_tf32_kernel,
                         cudaFuncAttributeMaxDynamicSharedMemorySize, gemm_smem);
    cudaFuncSetAttribute(flash_bf16_kernel,
                         cudaFuncAttributeMaxDynamicSharedMemorySize, attn_smem);

    const int M = BATCH * SEQ;                    // 4096
    dim3 qkv_grid(DMODEL / 128, M / 128, 3);      // (4, 32, 3) fused QKV
    dim3 gemm_grid(DMODEL / 128, M / 128);        // (4, 32)

    gemm_qkv_kernel<<<qkv_grid, 256, gemm_smem>>>(q, k, v, Wq, Wk, Wv,
                                                  bq, bk, bv, pQ, pK, pV);

    dim3 attn_grid(BATCH, SEQ / 128, NHEADS);     // batch fastest -> bias L2 reuse
    flash_bf16_kernel<<<attn_grid, 256, attn_smem>>>(mask, bias);

    gemm_tf32_kernel<<<gemm_grid, 256, gemm_smem>>>(pC, Wo, bo, out, M, DMODEL, DMODEL, 1.0f);
}